// round 5
// baseline (speedup 1.0000x reference)
#include <cuda_runtime.h>
#include <math.h>

#define HH 1024
#define WW 1024
#define PLANE (HH * WW)

typedef unsigned long long u64;

// Scratch: pass1 output (transposed, [s][x][y]) and pass2 output ([s][y][x]).
__device__ float g_sc1[(size_t)52 * PLANE];
__device__ float g_sc2[(size_t)52 * PLANE];

// ---- packed f32x2 helpers (two independent IEEE-RN lane ops per instr) ----
__device__ __forceinline__ u64 pk2(float v) {
    u64 r; asm("mov.b64 %0, {%1, %1};" : "=l"(r) : "f"(v)); return r;
}
__device__ __forceinline__ u64 fma2(u64 a, u64 b, u64 c) {   // per-lane __fmaf_rn
    u64 d; asm("fma.rn.f32x2 %0, %1, %2, %3;" : "=l"(d) : "l"(a), "l"(b), "l"(c));
    return d;
}
__device__ __forceinline__ float lo2(u64 v) { return __uint_as_float((unsigned)v); }
__device__ __forceinline__ float hi2(u64 v) { return __uint_as_float((unsigned)(v >> 32)); }

// ---------------------------------------------------------------------------
// Pass 1: vertical conv, FMA numerics (ascending taps, single accumulator).
// Tile 64x x 64y. Thread = x-pair (2*tx) x 8 y-outputs, packed f32x2.
// Per-s kernel strip double-buffered in smem. Output transposed to
// g_sc1[s][x][y] via smem stage.
// ---------------------------------------------------------------------------
__global__ __launch_bounds__(256) void pass1_vert(
    const float* __restrict__ img, const float* __restrict__ k1,
    const float* __restrict__ sigmas, int S, int K, int RMAX)
{
    extern __shared__ float sm[];
    float* skb = sm;                       // 2 * 128 kernel strips
    float* simg = sm + 256;                // ROWS * 64
    const int ROWS = 64 + 2 * RMAX + 8;
    float* stage = simg + ROWS * 64;       // 64 * 65

    const int tid = threadIdx.x;
    const int tx = tid & 31, ty = tid >> 5;
    const int x0 = blockIdx.x * 64;
    const int y0 = blockIdx.y * 64;

    // strip for s=0
    for (int i = tid; i < 128; i += 256) skb[i] = (i < K) ? k1[i] : 0.0f;
    // image tile with max halo (shared across all sigmas); zero outside
    for (int i = tid; i < ROWS * 64; i += 256) {
        int rr = i >> 6, cc = i & 63;
        int gy = y0 - RMAX + rr;
        simg[i] = ((unsigned)gy < HH) ? img[gy * WW + x0 + cc] : 0.0f;
    }
    __syncthreads();

    const u64* colp = (const u64*)simg + tx;   // 32 u64 per row

    for (int s = 0; s < S; ++s) {
        // prefetch next kernel strip into the other buffer (visible after syncs)
        if (s + 1 < S) {
            float* nb = skb + ((s + 1) & 1) * 128;
            for (int i = tid; i < 128; i += 256)
                nb[i] = (i < K) ? k1[(s + 1) * K + i] : 0.0f;
        }

        float sg = sigmas[s];
        int r = (int)(5.0f * sg + 0.5f) + 1;
        if (r > RMAX) r = RMAX;
        const int lenp = (2 * r + 8) & ~7;          // mult of 8, >= 2r+1, pads hit k==0
        const float* kk = skb + (s & 1) * 128 + (RMAX - r);
        const int base = ty * 8 + (RMAX - r);

        u64 w[8], acc[8];
        #pragma unroll
        for (int j = 0; j < 8; ++j) { w[j] = colp[(base + j) * 32]; acc[j] = 0ull; }
        for (int u = 0; u < lenp; u += 8) {
            #pragma unroll
            for (int uu = 0; uu < 8; ++uu) {
                u64 kv2 = pk2(kk[u + uu]);
                #pragma unroll
                for (int j = 0; j < 8; ++j)
                    acc[j] = fma2(kv2, w[(uu + j) & 7], acc[j]);
                w[uu] = colp[(base + u + uu + 8) * 32];
            }
        }
        __syncthreads();   // prior stage reads done; strip prefetch visible next iter
        #pragma unroll
        for (int j = 0; j < 8; ++j) {
            stage[(2 * tx + 0) * 65 + ty * 8 + j] = lo2(acc[j]);
            stage[(2 * tx + 1) * 65 + ty * 8 + j] = hi2(acc[j]);
        }
        __syncthreads();
        float* op = g_sc1 + (size_t)s * PLANE + (size_t)x0 * HH + y0;
        for (int e = tid; e < 4096; e += 256) {
            int xo = e >> 6, yo = e & 63;
            op[(size_t)xo * HH + yo] = stage[xo * 65 + yo];
        }
    }
}

// ---------------------------------------------------------------------------
// Pass 2: horizontal conv on transposed planes, STRICT mul-then-add numerics
// (two roundings per tap). Implemented as two uncontractable packed FMAs:
//   p   = fma.rn(k, x, zero)  == rn(k*x)   (all operands >= 0, no -0 hazard)
//   acc = fma.rn(p, one, acc) == rn(acc+p)
// zero/one arrive as RUNTIME kernel args so neither nvcc nor ptxas can fold
// the FMAs back into mul/add (which -fmad=true would then re-contract).
// ---------------------------------------------------------------------------
__global__ __launch_bounds__(256) void pass2_horiz(
    const float* __restrict__ k1, const float* __restrict__ sigmas,
    int S, int K, int RMAX, float zero_rt, float one_rt)
{
    extern __shared__ float sm[];
    float* sk = sm;                        // 128
    float* stile = sm + 128;               // (64 + 2r + 8) * 64 worst-case
    float* stage = stile + (64 + 2 * RMAX + 8) * 64;  // 64 * 65

    const int tid = threadIdx.x;
    const int tx = tid & 31, ty = tid >> 5;
    const int y0 = blockIdx.x * 64;   // minor dim of transposed layout
    const int x0 = blockIdx.y * 64;   // conv dim
    const int s = blockIdx.z;

    const u64 zero2 = pk2(zero_rt);
    const u64 one2 = pk2(one_rt);

    float sg = sigmas[s];
    int r = (int)(5.0f * sg + 0.5f) + 1;
    if (r > RMAX) r = RMAX;

    for (int i = tid; i < 128; i += 256) sk[i] = (i < K) ? k1[s * K + i] : 0.0f;

    const int ROWS = 64 + 2 * r + 8;
    const float* ip = g_sc1 + (size_t)s * PLANE;
    for (int i = tid; i < ROWS * 64; i += 256) {
        int rr = i >> 6, cc = i & 63;
        int gx = x0 - r + rr;
        stile[i] = ((unsigned)gx < WW) ? ip[(size_t)gx * HH + y0 + cc] : 0.0f;
    }
    __syncthreads();

    const u64* colp = (const u64*)stile + tx;
    const float* kk = sk + (RMAX - r);
    const int base = ty * 8;
    const int lenp = (2 * r + 8) & ~7;

    u64 w[8], acc[8];
    #pragma unroll
    for (int j = 0; j < 8; ++j) { w[j] = colp[(base + j) * 32]; acc[j] = zero2; }
    for (int u = 0; u < lenp; u += 8) {
        #pragma unroll
        for (int uu = 0; uu < 8; ++uu) {
            u64 kv2 = pk2(kk[u + uu]);
            #pragma unroll
            for (int j = 0; j < 8; ++j) {
                u64 p = fma2(kv2, w[(uu + j) & 7], zero2);   // rn(k*x)
                acc[j] = fma2(p, one2, acc[j]);              // rn(acc + p)
            }
            w[uu] = colp[(base + u + uu + 8) * 32];
        }
    }
    #pragma unroll
    for (int j = 0; j < 8; ++j) {
        stage[(2 * tx + 0) * 65 + ty * 8 + j] = lo2(acc[j]);
        stage[(2 * tx + 1) * 65 + ty * 8 + j] = hi2(acc[j]);
    }
    __syncthreads();
    float* op = g_sc2 + (size_t)s * PLANE + (size_t)y0 * WW + x0;
    for (int e = tid; e < 4096; e += 256) {
        int yo = e >> 6, xo = e & 63;
        op[(size_t)yo * WW + xo] = stage[yo * 65 + xo];
    }
}

// ---------------------------------------------------------------------------
// Pass 3: fused DoG + 3x3x3 maxpool (pad -inf) + mask, rolling over scale s.
// ---------------------------------------------------------------------------
__global__ __launch_bounds__(256) void pass3_dog_nms(
    const float* __restrict__ sigmas, float* __restrict__ out,
    int S, size_t out_n)
{
    __shared__ float gb[2][34 * 36];
    __shared__ float db[2][34 * 36];
    __shared__ float m2[3][1024];

    const int tid = threadIdx.x;
    const int x0 = blockIdx.x * 32 - 1;
    const int y0 = blockIdx.y * 32 - 1;
    const float NINF = -INFINITY;
    const size_t n1 = (size_t)(S - 1) * PLANE;

    for (int i = tid; i < 3 * 1024; i += 256) (&m2[0][0])[i] = NINF;

    for (int s = 0; s <= S; ++s) {
        if (s < S) {
            const float* gp = g_sc2 + (size_t)s * PLANE;
            for (int i = tid; i < 34 * 34; i += 256) {
                int yy = i / 34, xx = i - yy * 34;
                int gy = y0 + yy, gx = x0 + xx;
                gb[s & 1][yy * 36 + xx] =
                    ((unsigned)gy < HH && (unsigned)gx < WW) ? gp[gy * WW + gx] : 0.0f;
            }
        }
        __syncthreads();
        if (s >= 1 && s < S) {
            float sg = sigmas[s - 1];
            for (int i = tid; i < 34 * 34; i += 256) {
                int yy = i / 34, xx = i - yy * 34;
                int gy = y0 + yy, gx = x0 + xx;
                float v = NINF;  // -inf outside image: matches maxpool padding
                if ((unsigned)gy < HH && (unsigned)gx < WW)
                    v = __fmul_rn(__fsub_rn(gb[(s - 1) & 1][yy * 36 + xx],
                                            gb[s & 1][yy * 36 + xx]), sg);
                db[(s - 1) & 1][yy * 36 + xx] = v;
            }
        } else if (s == S) {
            for (int i = tid; i < 1024; i += 256) m2[(S - 1) % 3][i] = NINF;
        }
        __syncthreads();
        if (s >= 1 && s < S) {
            int d = s - 1;
            const float* dp0 = &db[d & 1][0];
            for (int i = tid; i < 1024; i += 256) {
                int yy = i >> 5, xx = i & 31;
                const float* dp = dp0 + yy * 36 + xx;
                float m = fmaxf(fmaxf(dp[0], dp[1]), dp[2]);
                m = fmaxf(m, fmaxf(fmaxf(dp[36], dp[37]), dp[38]));
                m = fmaxf(m, fmaxf(fmaxf(dp[72], dp[73]), dp[74]));
                m2[d % 3][i] = m;
            }
        }
        __syncthreads();
        if (s >= 2) {
            int t = s - 2;
            for (int i = tid; i < 1024; i += 256) {
                int yy = i >> 5, xx = i & 31;
                float dv = db[t & 1][(yy + 1) * 36 + (xx + 1)];
                float p = fmaxf(fmaxf(m2[(t + 2) % 3][i], m2[t % 3][i]),
                                m2[(t + 1) % 3][i]);
                int gy = y0 + 1 + yy, gx = x0 + 1 + xx;
                size_t oidx = (size_t)t * PLANE + (size_t)gy * WW + gx;
                if (oidx < out_n) out[oidx] = dv;
                size_t midx = n1 + oidx;
                if (midx < out_n)
                    out[midx] = (dv == p && dv > 0.001f) ? 1.0f : 0.0f;
            }
        }
        __syncthreads();
    }
}

__global__ void zero_tail(float* p, size_t n)
{
    size_t i = (size_t)blockIdx.x * blockDim.x + threadIdx.x;
    if (i < n) p[i] = 0.0f;
}

extern "C" void kernel_launch(void* const* d_in, const int* in_sizes, int n_in,
                              void* d_out, int out_size)
{
    const float* img = (const float*)d_in[0];
    const float* k1  = (const float*)d_in[1];
    const float* sig = (const float*)d_in[2];
    int S = in_sizes[2];               // number of sigmas
    int K = in_sizes[1] / S;           // padded 1D kernel length
    int RMAX = (K - 1) / 2;
    float* out = (float*)d_out;
    size_t n1 = (size_t)(S - 1) * PLANE;
    size_t used = 2 * n1;
    size_t on = (size_t)out_size;

    int rows = 64 + 2 * RMAX + 8;
    size_t smem1 = (size_t)(256 + rows * 64 + 64 * 65) * sizeof(float);
    size_t smem2 = (size_t)(128 + rows * 64 + 64 * 65) * sizeof(float);
    cudaFuncSetAttribute(pass1_vert, cudaFuncAttributeMaxDynamicSharedMemorySize,
                         (int)smem1);
    cudaFuncSetAttribute(pass2_horiz, cudaFuncAttributeMaxDynamicSharedMemorySize,
                         (int)smem2);

    dim3 g1(WW / 64, HH / 64);
    pass1_vert<<<g1, 256, smem1>>>(img, k1, sig, S, K, RMAX);

    // zero_rt/one_rt as runtime args: opaque to constant folding.
    volatile float z = 0.0f, o = 1.0f;
    dim3 g2(HH / 64, WW / 64, S);
    pass2_horiz<<<g2, 256, smem2>>>(k1, sig, S, K, RMAX, z, o);

    dim3 g3(WW / 32, HH / 32);
    pass3_dog_nms<<<g3, 256>>>(sig, out, S, on);

    if (on > used) {
        size_t rem = on - used;
        int blocks = (int)((rem + 255) / 256);
        zero_tail<<<blocks, 256>>>(out + used, rem);
    }
}

// round 7
// speedup vs baseline: 1.0537x; 1.0537x over previous
#include <cuda_runtime.h>
#include <math.h>

#define HH 1024
#define WW 1024
#define PLANE (HH * WW)

typedef unsigned long long u64;

// Scratch: pass1 output (transposed, [s][x][y]) and pass2 output ([s][y][x]).
__device__ float g_sc1[(size_t)52 * PLANE];
__device__ float g_sc2[(size_t)52 * PLANE];

// ---- packed f32x2 helpers (two independent IEEE-RN lane ops per instr) ----
__device__ __forceinline__ u64 pk2(float v) {
    u64 r; asm("mov.b64 %0, {%1, %1};" : "=l"(r) : "f"(v)); return r;
}
__device__ __forceinline__ u64 fma2(u64 a, u64 b, u64 c) {   // per-lane __fmaf_rn
    u64 d; asm("fma.rn.f32x2 %0, %1, %2, %3;" : "=l"(d) : "l"(a), "l"(b), "l"(c));
    return d;
}
__device__ __forceinline__ float lo2(u64 v) { return __uint_as_float((unsigned)v); }
__device__ __forceinline__ float hi2(u64 v) { return __uint_as_float((unsigned)(v >> 32)); }

// ---------------------------------------------------------------------------
// Pass 1: vertical conv, FMA numerics (ascending taps, single accumulator).
// 512 threads. Tile 64x x 64y; thread = x-pair (2*tx) x 4 y-outputs (f32x2).
// grid.z splits the sigma range into chunks for SM load balance.
// Kernel-strip double buffer indexed by absolute s parity (init strip goes
// into (s_beg & 1) — the R6 bug was loading it into buffer 0 always).
// ---------------------------------------------------------------------------
__global__ __launch_bounds__(512) void pass1_vert(
    const float* __restrict__ img, const float* __restrict__ k1,
    const float* __restrict__ sigmas, int S, int K, int RMAX, int SCHUNK)
{
    extern __shared__ float sm[];
    float* skb = sm;                       // 2 * 128 kernel strips
    float* simg = sm + 256;                // ROWS * 64
    const int ROWS = 64 + 2 * RMAX + 8;
    float* stage = simg + ROWS * 64;       // 64 * 65

    const int tid = threadIdx.x;
    const int tx = tid & 31, ty = tid >> 5;          // ty in 0..15
    const int x0 = blockIdx.x * 64;
    const int y0 = blockIdx.y * 64;
    const int s_beg = blockIdx.z * SCHUNK;
    int s_end = s_beg + SCHUNK; if (s_end > S) s_end = S;

    // strip for first sigma of this chunk — parity-correct buffer!
    {
        float* fb = skb + (s_beg & 1) * 128;
        for (int i = tid; i < 128; i += 512) fb[i] = (i < K) ? k1[s_beg * K + i] : 0.0f;
    }
    // image tile with max halo (shared across chunk's sigmas); zero outside
    for (int i = tid; i < ROWS * 64; i += 512) {
        int rr = i >> 6, cc = i & 63;
        int gy = y0 - RMAX + rr;
        simg[i] = ((unsigned)gy < HH) ? img[gy * WW + x0 + cc] : 0.0f;
    }
    __syncthreads();

    const u64* colp = (const u64*)simg + tx;   // 32 u64 per row

    for (int s = s_beg; s < s_end; ++s) {
        // prefetch next kernel strip into the other buffer
        if (s + 1 < s_end) {
            float* nb = skb + ((s + 1) & 1) * 128;
            for (int i = tid; i < 128; i += 512)
                nb[i] = (i < K) ? k1[(s + 1) * K + i] : 0.0f;
        }

        float sg = sigmas[s];
        int r = (int)(5.0f * sg + 0.5f) + 1;
        if (r > RMAX) r = RMAX;
        const int lenp = (2 * r + 4) & ~3;          // mult of 4, >= 2r+1, pads hit k==0
        const float* kk = skb + (s & 1) * 128 + (RMAX - r);
        const int base = ty * 4 + (RMAX - r);

        u64 w[4], acc[4];
        #pragma unroll
        for (int j = 0; j < 4; ++j) { w[j] = colp[(base + j) * 32]; acc[j] = 0ull; }
        for (int u = 0; u < lenp; u += 4) {
            #pragma unroll
            for (int uu = 0; uu < 4; ++uu) {
                u64 kv2 = pk2(kk[u + uu]);
                #pragma unroll
                for (int j = 0; j < 4; ++j)
                    acc[j] = fma2(kv2, w[(uu + j) & 3], acc[j]);
                w[uu] = colp[(base + u + uu + 4) * 32];
            }
        }
        __syncthreads();   // prior stage reads done; strip prefetch visible next iter
        #pragma unroll
        for (int j = 0; j < 4; ++j) {
            stage[(2 * tx + 0) * 65 + ty * 4 + j] = lo2(acc[j]);
            stage[(2 * tx + 1) * 65 + ty * 4 + j] = hi2(acc[j]);
        }
        __syncthreads();
        float* op = g_sc1 + (size_t)s * PLANE + (size_t)x0 * HH + y0;
        for (int e = tid; e < 4096; e += 512) {
            int xo = e >> 6, yo = e & 63;
            op[(size_t)xo * HH + yo] = stage[xo * 65 + yo];
        }
    }
}

// ---------------------------------------------------------------------------
// Pass 2: horizontal conv on transposed planes, STRICT mul-then-add numerics
// (two roundings per tap) via uncontractable packed FMAs:
//   p   = fma.rn(k, x, zero)  == rn(k*x)   (operands >= 0, no -0 hazard)
//   acc = fma.rn(p, one, acc) == rn(acc+p)
// zero/one are runtime args so no compiler can fold the FMAs into mul/add.
// 512 threads; thread = y-pair x 4 x-outputs.
// ---------------------------------------------------------------------------
__global__ __launch_bounds__(512) void pass2_horiz(
    const float* __restrict__ k1, const float* __restrict__ sigmas,
    int S, int K, int RMAX, float zero_rt, float one_rt)
{
    extern __shared__ float sm[];
    float* sk = sm;                        // 128
    float* stile = sm + 128;               // (64 + 2*RMAX + 8) * 64
    float* stage = stile + (64 + 2 * RMAX + 8) * 64;  // 64 * 65

    const int tid = threadIdx.x;
    const int tx = tid & 31, ty = tid >> 5;
    const int y0 = blockIdx.x * 64;   // minor dim of transposed layout
    const int x0 = blockIdx.y * 64;   // conv dim
    const int s = blockIdx.z;

    const u64 zero2 = pk2(zero_rt);
    const u64 one2 = pk2(one_rt);

    float sg = sigmas[s];
    int r = (int)(5.0f * sg + 0.5f) + 1;
    if (r > RMAX) r = RMAX;

    for (int i = tid; i < 128; i += 512) sk[i] = (i < K) ? k1[s * K + i] : 0.0f;

    const int ROWS = 64 + 2 * r + 8;
    const float* ip = g_sc1 + (size_t)s * PLANE;
    for (int i = tid; i < ROWS * 64; i += 512) {
        int rr = i >> 6, cc = i & 63;
        int gx = x0 - r + rr;
        stile[i] = ((unsigned)gx < WW) ? ip[(size_t)gx * HH + y0 + cc] : 0.0f;
    }
    __syncthreads();

    const u64* colp = (const u64*)stile + tx;
    const float* kk = sk + (RMAX - r);
    const int base = ty * 4;
    const int lenp = (2 * r + 4) & ~3;

    u64 w[4], acc[4];
    #pragma unroll
    for (int j = 0; j < 4; ++j) { w[j] = colp[(base + j) * 32]; acc[j] = zero2; }
    for (int u = 0; u < lenp; u += 4) {
        #pragma unroll
        for (int uu = 0; uu < 4; ++uu) {
            u64 kv2 = pk2(kk[u + uu]);
            #pragma unroll
            for (int j = 0; j < 4; ++j) {
                u64 p = fma2(kv2, w[(uu + j) & 3], zero2);   // rn(k*x)
                acc[j] = fma2(p, one2, acc[j]);              // rn(acc + p)
            }
            w[uu] = colp[(base + u + uu + 4) * 32];
        }
    }
    #pragma unroll
    for (int j = 0; j < 4; ++j) {
        stage[(2 * tx + 0) * 65 + ty * 4 + j] = lo2(acc[j]);
        stage[(2 * tx + 1) * 65 + ty * 4 + j] = hi2(acc[j]);
    }
    __syncthreads();
    float* op = g_sc2 + (size_t)s * PLANE + (size_t)y0 * WW + x0;
    for (int e = tid; e < 4096; e += 512) {
        int yo = e >> 6, xo = e & 63;
        op[(size_t)yo * WW + xo] = stage[yo * 65 + xo];
    }
}

// ---------------------------------------------------------------------------
// Pass 3: fused DoG + 3x3x3 maxpool (pad -inf) + mask, rolling over scale s.
// ---------------------------------------------------------------------------
__global__ __launch_bounds__(256) void pass3_dog_nms(
    const float* __restrict__ sigmas, float* __restrict__ out,
    int S, size_t out_n)
{
    __shared__ float gb[2][34 * 36];
    __shared__ float db[2][34 * 36];
    __shared__ float m2[3][1024];

    const int tid = threadIdx.x;
    const int x0 = blockIdx.x * 32 - 1;
    const int y0 = blockIdx.y * 32 - 1;
    const float NINF = -INFINITY;
    const size_t n1 = (size_t)(S - 1) * PLANE;

    for (int i = tid; i < 3 * 1024; i += 256) (&m2[0][0])[i] = NINF;

    for (int s = 0; s <= S; ++s) {
        if (s < S) {
            const float* gp = g_sc2 + (size_t)s * PLANE;
            for (int i = tid; i < 34 * 34; i += 256) {
                int yy = i / 34, xx = i - yy * 34;
                int gy = y0 + yy, gx = x0 + xx;
                gb[s & 1][yy * 36 + xx] =
                    ((unsigned)gy < HH && (unsigned)gx < WW) ? gp[gy * WW + gx] : 0.0f;
            }
        }
        __syncthreads();
        if (s >= 1 && s < S) {
            float sg = sigmas[s - 1];
            for (int i = tid; i < 34 * 34; i += 256) {
                int yy = i / 34, xx = i - yy * 34;
                int gy = y0 + yy, gx = x0 + xx;
                float v = NINF;  // -inf outside image: matches maxpool padding
                if ((unsigned)gy < HH && (unsigned)gx < WW)
                    v = __fmul_rn(__fsub_rn(gb[(s - 1) & 1][yy * 36 + xx],
                                            gb[s & 1][yy * 36 + xx]), sg);
                db[(s - 1) & 1][yy * 36 + xx] = v;
            }
        } else if (s == S) {
            for (int i = tid; i < 1024; i += 256) m2[(S - 1) % 3][i] = NINF;
        }
        __syncthreads();
        if (s >= 1 && s < S) {
            int d = s - 1;
            const float* dp0 = &db[d & 1][0];
            for (int i = tid; i < 1024; i += 256) {
                int yy = i >> 5, xx = i & 31;
                const float* dp = dp0 + yy * 36 + xx;
                float m = fmaxf(fmaxf(dp[0], dp[1]), dp[2]);
                m = fmaxf(m, fmaxf(fmaxf(dp[36], dp[37]), dp[38]));
                m = fmaxf(m, fmaxf(fmaxf(dp[72], dp[73]), dp[74]));
                m2[d % 3][i] = m;
            }
        }
        __syncthreads();
        if (s >= 2) {
            int t = s - 2;
            for (int i = tid; i < 1024; i += 256) {
                int yy = i >> 5, xx = i & 31;
                float dv = db[t & 1][(yy + 1) * 36 + (xx + 1)];
                float p = fmaxf(fmaxf(m2[(t + 2) % 3][i], m2[t % 3][i]),
                                m2[(t + 1) % 3][i]);
                int gy = y0 + 1 + yy, gx = x0 + 1 + xx;
                size_t oidx = (size_t)t * PLANE + (size_t)gy * WW + gx;
                if (oidx < out_n) out[oidx] = dv;
                size_t midx = n1 + oidx;
                if (midx < out_n)
                    out[midx] = (dv == p && dv > 0.001f) ? 1.0f : 0.0f;
            }
        }
        __syncthreads();
    }
}

__global__ void zero_tail(float* p, size_t n)
{
    size_t i = (size_t)blockIdx.x * blockDim.x + threadIdx.x;
    if (i < n) p[i] = 0.0f;
}

extern "C" void kernel_launch(void* const* d_in, const int* in_sizes, int n_in,
                              void* d_out, int out_size)
{
    const float* img = (const float*)d_in[0];
    const float* k1  = (const float*)d_in[1];
    const float* sig = (const float*)d_in[2];
    int S = in_sizes[2];               // number of sigmas
    int K = in_sizes[1] / S;           // padded 1D kernel length
    int RMAX = (K - 1) / 2;
    float* out = (float*)d_out;
    size_t n1 = (size_t)(S - 1) * PLANE;
    size_t used = 2 * n1;
    size_t on = (size_t)out_size;

    int rows = 64 + 2 * RMAX + 8;
    size_t smem1 = (size_t)(256 + rows * 64 + 64 * 65) * sizeof(float);
    size_t smem2 = (size_t)(128 + rows * 64 + 64 * 65) * sizeof(float);
    cudaFuncSetAttribute(pass1_vert, cudaFuncAttributeMaxDynamicSharedMemorySize,
                         (int)smem1);
    cudaFuncSetAttribute(pass2_horiz, cudaFuncAttributeMaxDynamicSharedMemorySize,
                         (int)smem2);

    const int NZ = 4;
    int schunk = (S + NZ - 1) / NZ;
    dim3 g1(WW / 64, HH / 64, NZ);
    pass1_vert<<<g1, 512, smem1>>>(img, k1, sig, S, K, RMAX, schunk);

    // zero_rt/one_rt as runtime args: opaque to constant folding.
    volatile float z = 0.0f, o = 1.0f;
    dim3 g2(HH / 64, WW / 64, S);
    pass2_horiz<<<g2, 512, smem2>>>(k1, sig, S, K, RMAX, z, o);

    dim3 g3(WW / 32, HH / 32);
    pass3_dog_nms<<<g3, 256>>>(sig, out, S, on);

    if (on > used) {
        size_t rem = on - used;
        int blocks = (int)((rem + 255) / 256);
        zero_tail<<<blocks, 256>>>(out + used, rem);
    }
}

// round 8
// speedup vs baseline: 1.0697x; 1.0152x over previous
#include <cuda_runtime.h>
#include <math.h>

#define HH 1024
#define WW 1024
#define PLANE (HH * WW)

typedef unsigned long long u64;

// Scratch: pass1 output (transposed, [s][x][y]) and pass2 output ([s][y][x]).
__device__ float g_sc1[(size_t)52 * PLANE];
__device__ float g_sc2[(size_t)52 * PLANE];

// ---- packed f32x2 helpers (two independent IEEE-RN lane ops per instr) ----
__device__ __forceinline__ u64 pk2(float v) {
    u64 r; asm("mov.b64 %0, {%1, %1};" : "=l"(r) : "f"(v)); return r;
}
__device__ __forceinline__ u64 fma2(u64 a, u64 b, u64 c) {   // per-lane __fmaf_rn
    u64 d; asm("fma.rn.f32x2 %0, %1, %2, %3;" : "=l"(d) : "l"(a), "l"(b), "l"(c));
    return d;
}
__device__ __forceinline__ float lo2(u64 v) { return __uint_as_float((unsigned)v); }
__device__ __forceinline__ float hi2(u64 v) { return __uint_as_float((unsigned)(v >> 32)); }

// ---------------------------------------------------------------------------
// Pass 1: vertical conv, FMA numerics (ascending taps, single accumulator).
// 512 threads, tile 64x x 128y; thread = x-pair (2*tx) x 8 y-outputs (f32x2)
// => 1 LDS.64 refill + 1 LDS.32 ktap per 8 FFMA2 (FMA-bound, not LSU-bound).
// Sigma chunks are STRIDED (chunk c: s = c, c+NZ, ...) for work balance;
// kernel-strip double buffer indexed by local iteration parity.
// ---------------------------------------------------------------------------
__global__ __launch_bounds__(512, 2) void pass1_vert(
    const float* __restrict__ img, const float* __restrict__ k1,
    const float* __restrict__ sigmas, int S, int K, int RMAX, int NZ)
{
    extern __shared__ float sm[];
    float* skb = sm;                       // 2 * 128 kernel strips
    float* simg = sm + 256;                // ROWS * 64
    const int ROWS = 128 + 2 * RMAX + 8;
    float* stage = simg + ROWS * 64;       // 64 * 129 (stage[x][y])

    const int tid = threadIdx.x;
    const int tx = tid & 31, ty = tid >> 5;          // ty in 0..15
    const int x0 = blockIdx.x * 64;
    const int y0 = blockIdx.y * 128;
    const int c = blockIdx.z;                        // sigma stride class

    // first strip (s = c) into buffer 0
    for (int i = tid; i < 128; i += 512) skb[i] = (i < K) ? k1[c * K + i] : 0.0f;
    // image tile with max halo (shared across this block's sigmas)
    for (int i = tid; i < ROWS * 64; i += 512) {
        int rr = i >> 6, cc = i & 63;
        int gy = y0 - RMAX + rr;
        simg[i] = ((unsigned)gy < HH) ? img[gy * WW + x0 + cc] : 0.0f;
    }
    __syncthreads();

    const u64* colp = (const u64*)simg + tx;   // 32 u64 per row

    int it = 0;
    for (int s = c; s < S; s += NZ, ++it) {
        // prefetch next strip (s+NZ) into the other buffer
        if (s + NZ < S) {
            float* nb = skb + ((it + 1) & 1) * 128;
            for (int i = tid; i < 128; i += 512)
                nb[i] = (i < K) ? k1[(s + NZ) * K + i] : 0.0f;
        }

        float sg = sigmas[s];
        int r = (int)(5.0f * sg + 0.5f) + 1;
        if (r > RMAX) r = RMAX;
        const int lenp = (2 * r + 8) & ~7;          // mult of 8; pads hit k==0
        const float* kk = skb + (it & 1) * 128 + (RMAX - r);
        const int base = ty * 8 + (RMAX - r);

        u64 w[8], acc[8];
        #pragma unroll
        for (int j = 0; j < 8; ++j) { w[j] = colp[(base + j) * 32]; acc[j] = 0ull; }
        for (int u = 0; u < lenp; u += 8) {
            #pragma unroll
            for (int uu = 0; uu < 8; ++uu) {
                u64 kv2 = pk2(kk[u + uu]);
                #pragma unroll
                for (int j = 0; j < 8; ++j)
                    acc[j] = fma2(kv2, w[(uu + j) & 7], acc[j]);
                w[uu] = colp[(base + u + uu + 8) * 32];
            }
        }
        __syncthreads();   // prior stage reads done; strip prefetch visible next iter
        #pragma unroll
        for (int j = 0; j < 8; ++j) {
            stage[(2 * tx + 0) * 129 + ty * 8 + j] = lo2(acc[j]);
            stage[(2 * tx + 1) * 129 + ty * 8 + j] = hi2(acc[j]);
        }
        __syncthreads();
        float* op = g_sc1 + (size_t)s * PLANE + (size_t)x0 * HH + y0;
        for (int e = tid; e < 8192; e += 512) {
            int xo = e >> 7, yo = e & 127;   // consecutive e -> consecutive yo
            op[(size_t)xo * HH + yo] = stage[xo * 129 + yo];
        }
    }
}

// ---------------------------------------------------------------------------
// Pass 2: horizontal conv on transposed planes, STRICT mul-then-add numerics
// (two roundings per tap) via uncontractable packed FMAs:
//   p   = fma.rn(k, x, zero)  == rn(k*x)   (operands >= 0, no -0 hazard)
//   acc = fma.rn(p, one, acc) == rn(acc+p)
// zero/one are runtime args so no compiler can fold the FMAs into mul/add.
// 512 threads; tile 64 minor(y) x 128 conv(x); thread = y-pair x 8 x-outputs.
// ---------------------------------------------------------------------------
__global__ __launch_bounds__(512, 2) void pass2_horiz(
    const float* __restrict__ k1, const float* __restrict__ sigmas,
    int S, int K, int RMAX, float zero_rt, float one_rt)
{
    extern __shared__ float sm[];
    float* sk = sm;                        // 128
    float* stile = sm + 128;               // (128 + 2*RMAX + 8) * 64
    float* stage = stile + (128 + 2 * RMAX + 8) * 64;  // 64 * 129 (stage[y][x])

    const int tid = threadIdx.x;
    const int tx = tid & 31, ty = tid >> 5;
    const int y0 = blockIdx.x * 64;   // minor dim of transposed layout
    const int x0 = blockIdx.y * 128;  // conv dim
    const int s = blockIdx.z;

    const u64 zero2 = pk2(zero_rt);
    const u64 one2 = pk2(one_rt);

    float sg = sigmas[s];
    int r = (int)(5.0f * sg + 0.5f) + 1;
    if (r > RMAX) r = RMAX;

    for (int i = tid; i < 128; i += 512) sk[i] = (i < K) ? k1[s * K + i] : 0.0f;

    const int ROWS = 128 + 2 * r + 8;
    const float* ip = g_sc1 + (size_t)s * PLANE;
    for (int i = tid; i < ROWS * 64; i += 512) {
        int rr = i >> 6, cc = i & 63;
        int gx = x0 - r + rr;
        stile[i] = ((unsigned)gx < WW) ? ip[(size_t)gx * HH + y0 + cc] : 0.0f;
    }
    __syncthreads();

    const u64* colp = (const u64*)stile + tx;
    const float* kk = sk + (RMAX - r);
    const int base = ty * 8;
    const int lenp = (2 * r + 8) & ~7;

    u64 w[8], acc[8];
    #pragma unroll
    for (int j = 0; j < 8; ++j) { w[j] = colp[(base + j) * 32]; acc[j] = zero2; }
    for (int u = 0; u < lenp; u += 8) {
        #pragma unroll
        for (int uu = 0; uu < 8; ++uu) {
            u64 kv2 = pk2(kk[u + uu]);
            #pragma unroll
            for (int j = 0; j < 8; ++j) {
                u64 p = fma2(kv2, w[(uu + j) & 7], zero2);   // rn(k*x)
                acc[j] = fma2(p, one2, acc[j]);              // rn(acc + p)
            }
            w[uu] = colp[(base + u + uu + 8) * 32];
        }
    }
    #pragma unroll
    for (int j = 0; j < 8; ++j) {
        stage[(2 * tx + 0) * 129 + ty * 8 + j] = lo2(acc[j]);
        stage[(2 * tx + 1) * 129 + ty * 8 + j] = hi2(acc[j]);
    }
    __syncthreads();
    float* op = g_sc2 + (size_t)s * PLANE + (size_t)y0 * WW + x0;
    for (int e = tid; e < 8192; e += 512) {
        int yo = e >> 7, xo = e & 127;   // consecutive e -> consecutive xo
        op[(size_t)yo * WW + xo] = stage[yo * 129 + xo];
    }
}

// ---------------------------------------------------------------------------
// Pass 3: fused DoG + 3x3x3 maxpool (pad -inf) + mask, rolling over scale s.
// ---------------------------------------------------------------------------
__global__ __launch_bounds__(256) void pass3_dog_nms(
    const float* __restrict__ sigmas, float* __restrict__ out,
    int S, size_t out_n)
{
    __shared__ float gb[2][34 * 36];
    __shared__ float db[2][34 * 36];
    __shared__ float m2[3][1024];

    const int tid = threadIdx.x;
    const int x0 = blockIdx.x * 32 - 1;
    const int y0 = blockIdx.y * 32 - 1;
    const float NINF = -INFINITY;
    const size_t n1 = (size_t)(S - 1) * PLANE;

    for (int i = tid; i < 3 * 1024; i += 256) (&m2[0][0])[i] = NINF;

    for (int s = 0; s <= S; ++s) {
        if (s < S) {
            const float* gp = g_sc2 + (size_t)s * PLANE;
            for (int i = tid; i < 34 * 34; i += 256) {
                int yy = i / 34, xx = i - yy * 34;
                int gy = y0 + yy, gx = x0 + xx;
                gb[s & 1][yy * 36 + xx] =
                    ((unsigned)gy < HH && (unsigned)gx < WW) ? gp[gy * WW + gx] : 0.0f;
            }
        }
        __syncthreads();
        if (s >= 1 && s < S) {
            float sg = sigmas[s - 1];
            for (int i = tid; i < 34 * 34; i += 256) {
                int yy = i / 34, xx = i - yy * 34;
                int gy = y0 + yy, gx = x0 + xx;
                float v = NINF;  // -inf outside image: matches maxpool padding
                if ((unsigned)gy < HH && (unsigned)gx < WW)
                    v = __fmul_rn(__fsub_rn(gb[(s - 1) & 1][yy * 36 + xx],
                                            gb[s & 1][yy * 36 + xx]), sg);
                db[(s - 1) & 1][yy * 36 + xx] = v;
            }
        } else if (s == S) {
            for (int i = tid; i < 1024; i += 256) m2[(S - 1) % 3][i] = NINF;
        }
        __syncthreads();
        if (s >= 1 && s < S) {
            int d = s - 1;
            const float* dp0 = &db[d & 1][0];
            for (int i = tid; i < 1024; i += 256) {
                int yy = i >> 5, xx = i & 31;
                const float* dp = dp0 + yy * 36 + xx;
                float m = fmaxf(fmaxf(dp[0], dp[1]), dp[2]);
                m = fmaxf(m, fmaxf(fmaxf(dp[36], dp[37]), dp[38]));
                m = fmaxf(m, fmaxf(fmaxf(dp[72], dp[73]), dp[74]));
                m2[d % 3][i] = m;
            }
        }
        __syncthreads();
        if (s >= 2) {
            int t = s - 2;
            for (int i = tid; i < 1024; i += 256) {
                int yy = i >> 5, xx = i & 31;
                float dv = db[t & 1][(yy + 1) * 36 + (xx + 1)];
                float p = fmaxf(fmaxf(m2[(t + 2) % 3][i], m2[t % 3][i]),
                                m2[(t + 1) % 3][i]);
                int gy = y0 + 1 + yy, gx = x0 + 1 + xx;
                size_t oidx = (size_t)t * PLANE + (size_t)gy * WW + gx;
                if (oidx < out_n) out[oidx] = dv;
                size_t midx = n1 + oidx;
                if (midx < out_n)
                    out[midx] = (dv == p && dv > 0.001f) ? 1.0f : 0.0f;
            }
        }
        __syncthreads();
    }
}

__global__ void zero_tail(float* p, size_t n)
{
    size_t i = (size_t)blockIdx.x * blockDim.x + threadIdx.x;
    if (i < n) p[i] = 0.0f;
}

extern "C" void kernel_launch(void* const* d_in, const int* in_sizes, int n_in,
                              void* d_out, int out_size)
{
    const float* img = (const float*)d_in[0];
    const float* k1  = (const float*)d_in[1];
    const float* sig = (const float*)d_in[2];
    int S = in_sizes[2];               // number of sigmas
    int K = in_sizes[1] / S;           // padded 1D kernel length
    int RMAX = (K - 1) / 2;
    float* out = (float*)d_out;
    size_t n1 = (size_t)(S - 1) * PLANE;
    size_t used = 2 * n1;
    size_t on = (size_t)out_size;

    int rows = 128 + 2 * RMAX + 8;
    size_t smem1 = (size_t)(256 + rows * 64 + 64 * 129) * sizeof(float);
    size_t smem2 = (size_t)(128 + rows * 64 + 64 * 129) * sizeof(float);
    cudaFuncSetAttribute(pass1_vert, cudaFuncAttributeMaxDynamicSharedMemorySize,
                         (int)smem1);
    cudaFuncSetAttribute(pass2_horiz, cudaFuncAttributeMaxDynamicSharedMemorySize,
                         (int)smem2);

    const int NZ = 8;                  // strided sigma classes for balance
    dim3 g1(WW / 64, HH / 128, NZ);
    pass1_vert<<<g1, 512, smem1>>>(img, k1, sig, S, K, RMAX, NZ);

    // zero_rt/one_rt as runtime args: opaque to constant folding.
    volatile float z = 0.0f, o = 1.0f;
    dim3 g2(HH / 64, WW / 128, S);
    pass2_horiz<<<g2, 512, smem2>>>(k1, sig, S, K, RMAX, z, o);

    dim3 g3(WW / 32, HH / 32);
    pass3_dog_nms<<<g3, 256>>>(sig, out, S, on);

    if (on > used) {
        size_t rem = on - used;
        int blocks = (int)((rem + 255) / 256);
        zero_tail<<<blocks, 256>>>(out + used, rem);
    }
}